// round 2
// baseline (speedup 1.0000x reference)
#include <cuda_runtime.h>
#include <cuda_fp16.h>
#include <cstdint>
#include <cstddef>

// Problem constants (fixed by dataset)
#define T_TOT 131072
#define CDIM  512
#define NF    1024   // [y(512) | z(512)]
#define BATCH 128

// ---------------- scratch: __device__ globals (no allocation allowed) ----------------
__device__ __half g_x[(size_t)T_TOT * CDIM];     // LN output fp16           134 MB
__device__ __half g_yz[(size_t)T_TOT * NF];      // [y|z] fp16               268 MB
__device__ __half g_wcat[(size_t)NF * CDIM];     // [W1 ; W2@W1] fp16, K-major
__device__ float  g_bcat[NF];                    // [b1 ; W2@b1+b2]
__device__ int    g_off[BATCH + 1];              // segment offsets

// ---------------- K0: segment offsets via binary search ----------------
__global__ void k_offsets(const int* __restrict__ batch) {
    int b = threadIdx.x;
    if (b <= BATCH) {
        int lo = 0, hi = T_TOT;
        while (lo < hi) {
            int mid = (lo + hi) >> 1;
            if (batch[mid] < b) lo = mid + 1; else hi = mid;
        }
        g_off[b] = lo;
    }
}

// ---------------- K1a: copy W1 -> wcat rows [0,512) fp16 ----------------
__global__ void k_wcopy(const float* __restrict__ W1) {
    int i = blockIdx.x * 256 + threadIdx.x;   // grid 1024 x 256 = 262144
    g_wcat[i] = __float2half(W1[i]);
}

// ---------------- K1b: bcat = [b1 ; W2@b1 + b2] ----------------
__global__ void k_bcat(const float* __restrict__ W2, const float* __restrict__ b1,
                       const float* __restrict__ b2) {
    __shared__ float sb1[CDIM];
    int t = threadIdx.x;                       // 512 threads
    sb1[t] = b1[t];
    __syncthreads();
    float acc = b2[t];
    const float* row = W2 + (size_t)t * CDIM;
    for (int j = 0; j < CDIM; j++) acc += row[j] * sb1[j];
    g_bcat[t] = b1[t];
    g_bcat[CDIM + t] = acc;
}

// ---------------- K1c: W21 = W2 @ W1 (fp32 accum) -> wcat rows [512,1024) fp16 ------
__global__ void k_w21(const float* __restrict__ W2, const float* __restrict__ W1) {
    __shared__ float sW2[16 * CDIM];           // 32 KB: 16 rows of W2
    int t = threadIdx.x;                       // 256 threads
    int d0 = blockIdx.x * 16;                  // 32 blocks
    for (int i = t; i < 16 * CDIM; i += 256) sW2[i] = W2[(size_t)d0 * CDIM + i];
    __syncthreads();
    float acc[16][2];
#pragma unroll
    for (int dl = 0; dl < 16; dl++) { acc[dl][0] = 0.f; acc[dl][1] = 0.f; }
    int k0 = t, k1 = t + 256;
    for (int j = 0; j < CDIM; j++) {
        float a0 = W1[(size_t)j * CDIM + k0];
        float a1 = W1[(size_t)j * CDIM + k1];
#pragma unroll
        for (int dl = 0; dl < 16; dl++) {
            float w = sW2[dl * CDIM + j];
            acc[dl][0] += w * a0;
            acc[dl][1] += w * a1;
        }
    }
#pragma unroll
    for (int dl = 0; dl < 16; dl++) {
        g_wcat[(size_t)(CDIM + d0 + dl) * CDIM + k0] = __float2half(acc[dl][0]);
        g_wcat[(size_t)(CDIM + d0 + dl) * CDIM + k1] = __float2half(acc[dl][1]);
    }
}

// ---------------- K2: LayerNorm (eps=1e-5) -> fp16 ----------------
__global__ void k_ln(const float* __restrict__ hs, const float* __restrict__ gamma,
                     const float* __restrict__ beta) {
    __shared__ float s_sum[4], s_sq[4];
    int row = blockIdx.x;
    int t = threadIdx.x;                       // 128 threads, 4 floats each
    const float4 v = __ldg((const float4*)(hs + (size_t)row * CDIM) + t);
    float s = v.x + v.y + v.z + v.w;
    float q = v.x * v.x + v.y * v.y + v.z * v.z + v.w * v.w;
#pragma unroll
    for (int o = 16; o > 0; o >>= 1) {
        s += __shfl_xor_sync(0xFFFFFFFFu, s, o);
        q += __shfl_xor_sync(0xFFFFFFFFu, q, o);
    }
    if ((t & 31) == 0) { s_sum[t >> 5] = s; s_sq[t >> 5] = q; }
    __syncthreads();
    s = s_sum[0] + s_sum[1] + s_sum[2] + s_sum[3];
    q = s_sq[0] + s_sq[1] + s_sq[2] + s_sq[3];
    float mu = s * (1.f / CDIM);
    float var = q * (1.f / CDIM) - mu * mu;
    float rs = rsqrtf(var + 1e-5f);
    float4 g4 = __ldg((const float4*)gamma + t);
    float4 b4 = __ldg((const float4*)beta + t);
    __half2 h0 = __floats2half2_rn((v.x - mu) * rs * g4.x + b4.x,
                                   (v.y - mu) * rs * g4.y + b4.y);
    __half2 h1 = __floats2half2_rn((v.z - mu) * rs * g4.z + b4.z,
                                   (v.w - mu) * rs * g4.w + b4.w);
    uint2 packed;
    packed.x = *(uint32_t*)&h0;
    packed.y = *(uint32_t*)&h1;
    *((uint2*)(g_x + (size_t)row * CDIM) + t) = packed;
}

// ---------------- K3: GEMM  yz[T,1024] = x[T,512] @ wcat^T + bcat -------------------
// CTA tile 128x128, k-chunk 64, double-buffered cp.async, mma.sync m16n8k16 f16->f32.
// smem rows padded to 72 halfs (144B) for conflict-free ldmatrix.
__device__ __forceinline__ uint32_t smem_u32(const void* p) {
    return (uint32_t)__cvta_generic_to_shared(p);
}

__global__ void __launch_bounds__(256, 2) k_gemm() {
    extern __shared__ __half sm[];
    const int tid = threadIdx.x;
    const int lane = tid & 31, wid = tid >> 5;
    const int n0 = blockIdx.x * 128;           // output-feature tile (8 tiles)
    const int row0 = blockIdx.y * 128;         // row tile (1024 tiles)
    __half* As[2] = { sm,         sm + 9216 };
    __half* Bs[2] = { sm + 18432, sm + 27648 };

    float acc[2][8][4];
#pragma unroll
    for (int a = 0; a < 2; a++)
#pragma unroll
        for (int b = 0; b < 8; b++)
#pragma unroll
            for (int c = 0; c < 4; c++) acc[a][b][c] = 0.f;

    auto load_chunk = [&](int kc, int bufi) {
        int k0 = kc * 64;
#pragma unroll
        for (int i = 0; i < 4; i++) {
            int sidx = tid + i * 256;
            int r = sidx >> 3, c = sidx & 7;   // 128 rows x 8 16B-chunks
            const __half* ga = g_x + (size_t)(row0 + r) * CDIM + k0 + c * 8;
            uint32_t sa = smem_u32(As[bufi] + r * 72 + c * 8);
            asm volatile("cp.async.cg.shared.global [%0], [%1], 16;\n" :: "r"(sa), "l"(ga));
            const __half* gb = g_wcat + (size_t)(n0 + r) * CDIM + k0 + c * 8;
            uint32_t sb = smem_u32(Bs[bufi] + r * 72 + c * 8);
            asm volatile("cp.async.cg.shared.global [%0], [%1], 16;\n" :: "r"(sb), "l"(gb));
        }
        asm volatile("cp.async.commit_group;\n");
    };

    load_chunk(0, 0);
    int buf = 0;
    const int wm = (wid & 3) * 32;             // 4 warps along M
    const int wn = (wid >> 2) * 64;            // 2 warps along N

    for (int kc = 0; kc < 8; kc++) {
        if (kc < 7) {
            load_chunk(kc + 1, buf ^ 1);
            asm volatile("cp.async.wait_group 1;\n");
        } else {
            asm volatile("cp.async.wait_group 0;\n");
        }
        __syncthreads();
#pragma unroll
        for (int kk = 0; kk < 4; kk++) {
            uint32_t a_r[2][4];
#pragma unroll
            for (int tm = 0; tm < 2; tm++) {
                uint32_t addr = smem_u32(As[buf] + (wm + tm * 16 + (lane & 15)) * 72
                                         + kk * 16 + (lane >> 4) * 8);
                asm volatile("ldmatrix.sync.aligned.m8n8.x4.shared.b16 {%0,%1,%2,%3}, [%4];\n"
                             : "=r"(a_r[tm][0]), "=r"(a_r[tm][1]),
                               "=r"(a_r[tm][2]), "=r"(a_r[tm][3]) : "r"(addr));
            }
            uint32_t b_r[4][4];
#pragma unroll
            for (int bp = 0; bp < 4; bp++) {
                uint32_t addr = smem_u32(Bs[buf] + (wn + bp * 16 + (lane & 7) + ((lane >> 4) << 3)) * 72
                                         + kk * 16 + (((lane >> 3) & 1) << 3));
                asm volatile("ldmatrix.sync.aligned.m8n8.x4.shared.b16 {%0,%1,%2,%3}, [%4];\n"
                             : "=r"(b_r[bp][0]), "=r"(b_r[bp][1]),
                               "=r"(b_r[bp][2]), "=r"(b_r[bp][3]) : "r"(addr));
            }
#pragma unroll
            for (int tm = 0; tm < 2; tm++) {
#pragma unroll
                for (int bp = 0; bp < 4; bp++) {
                    asm volatile("mma.sync.aligned.m16n8k16.row.col.f32.f16.f16.f32 "
                                 "{%0,%1,%2,%3}, {%4,%5,%6,%7}, {%8,%9}, {%0,%1,%2,%3};\n"
                                 : "+f"(acc[tm][bp * 2][0]), "+f"(acc[tm][bp * 2][1]),
                                   "+f"(acc[tm][bp * 2][2]), "+f"(acc[tm][bp * 2][3])
                                 : "r"(a_r[tm][0]), "r"(a_r[tm][1]), "r"(a_r[tm][2]), "r"(a_r[tm][3]),
                                   "r"(b_r[bp][0]), "r"(b_r[bp][1]));
                    asm volatile("mma.sync.aligned.m16n8k16.row.col.f32.f16.f16.f32 "
                                 "{%0,%1,%2,%3}, {%4,%5,%6,%7}, {%8,%9}, {%0,%1,%2,%3};\n"
                                 : "+f"(acc[tm][bp * 2 + 1][0]), "+f"(acc[tm][bp * 2 + 1][1]),
                                   "+f"(acc[tm][bp * 2 + 1][2]), "+f"(acc[tm][bp * 2 + 1][3])
                                 : "r"(a_r[tm][0]), "r"(a_r[tm][1]), "r"(a_r[tm][2]), "r"(a_r[tm][3]),
                                   "r"(b_r[bp][2]), "r"(b_r[bp][3]));
                }
            }
        }
        __syncthreads();
        buf ^= 1;
    }

    // epilogue: +bias, fp32 -> fp16, store to g_yz
#pragma unroll
    for (int tm = 0; tm < 2; tm++) {
        int r0e = row0 + wm + tm * 16 + (lane >> 2);
#pragma unroll
        for (int j = 0; j < 8; j++) {
            int gc = n0 + wn + j * 8 + (lane & 3) * 2;
            float bb0 = __ldg(&g_bcat[gc]);
            float bb1 = __ldg(&g_bcat[gc + 1]);
            __half2 h01 = __floats2half2_rn(acc[tm][j][0] + bb0, acc[tm][j][1] + bb1);
            __half2 h23 = __floats2half2_rn(acc[tm][j][2] + bb0, acc[tm][j][3] + bb1);
            *(__half2*)(g_yz + (size_t)r0e * NF + gc) = h01;
            *(__half2*)(g_yz + (size_t)(r0e + 8) * NF + gc) = h23;
        }
    }
}

// ---------------- K4: segment softmax-attention pooling ----------------
// One block per graph b; 1024 threads = 4 row-groups x 256 feature-pairs.
// No max subtraction needed: |z| bounded ~8 (LN'd inputs, bounded weights).
__global__ void k_reduce(float* __restrict__ out) {
    __shared__ float s_s[4][512], s_n[4][512];
    int b = blockIdx.x;
    int start = g_off[b], end = g_off[b + 1];
    int M = end - start;
    int tid = threadIdx.x;                     // 1024
    int p = tid & 255;                         // feature pair -> d = 2p, 2p+1
    int grp = tid >> 8;                        // 0..3 row groups
    int q = (M + 3) >> 2;
    int r0 = start + grp * q;
    int r1 = min(end, r0 + q);
    float2 s = make_float2(0.f, 0.f), num = make_float2(0.f, 0.f);
#pragma unroll 4
    for (int n = r0; n < r1; n++) {
        const __half2* base = (const __half2*)(g_yz + (size_t)n * NF);
        float2 yf = __half22float2(base[p]);
        float2 zf = __half22float2(base[256 + p]);
        float w0 = __expf(zf.x), w1 = __expf(zf.y);
        s.x += w0;  s.y += w1;
        num.x += w0 * yf.x;  num.y += w1 * yf.y;
    }
    s_s[grp][2 * p] = s.x;   s_s[grp][2 * p + 1] = s.y;
    s_n[grp][2 * p] = num.x; s_n[grp][2 * p + 1] = num.y;
    __syncthreads();
    if (tid < 512) {
        float S = s_s[0][tid] + s_s[1][tid] + s_s[2][tid] + s_s[3][tid];
        float N2 = s_n[0][tid] + s_n[1][tid] + s_n[2][tid] + s_n[3][tid];
        out[(size_t)b * 512 + tid] = (M > 0) ? (N2 / S) : 0.f;
    }
}

// ---------------- host launcher ----------------
extern "C" void kernel_launch(void* const* d_in, const int* in_sizes, int n_in,
                              void* d_out, int out_size) {
    const float* hs    = (const float*)d_in[0];
    const int*   batch = (const int*)d_in[1];
    // d_in[2] = max_nodes (unused)
    const float* gamma = (const float*)d_in[3];
    const float* beta  = (const float*)d_in[4];
    const float* W1    = (const float*)d_in[5];
    const float* b1    = (const float*)d_in[6];
    const float* W2    = (const float*)d_in[7];
    const float* b2    = (const float*)d_in[8];
    float* out = (float*)d_out;

    cudaFuncSetAttribute(k_gemm, cudaFuncAttributeMaxDynamicSharedMemorySize, 73728);

    k_offsets<<<1, 256>>>(batch);
    k_wcopy<<<1024, 256>>>(W1);
    k_bcat<<<1, 512>>>(W2, b1, b2);
    k_w21<<<32, 256>>>(W2, W1);
    k_ln<<<T_TOT, 128>>>(hs, gamma, beta);
    dim3 gg(8, 1024);
    k_gemm<<<gg, 256, 73728>>>();
    k_reduce<<<128, 1024>>>(out);
}

// round 3
// speedup vs baseline: 1.1572x; 1.1572x over previous
#include <cuda_runtime.h>
#include <cuda_fp16.h>
#include <cstdint>
#include <cstddef>

// Problem constants (fixed by dataset)
#define T_TOT 131072
#define CDIM  512
#define NF    1024   // interleaved [y_0,z_0,y_1,z_1,...]  (y=W1 path, z=W2W1 path)
#define BATCH 128

// ---------------- scratch: __device__ globals (no allocation allowed) ----------------
__device__ __half g_x[(size_t)T_TOT * CDIM];     // LN output fp16           134 MB
__device__ __half g_wcat[(size_t)NF * CDIM];     // interleaved weights, K-major (1 MB)
__device__ float  g_bcat[NF];                    // interleaved [b1_d ; (W2 b1 + b2)_d]
__device__ float  g_num[BATCH * CDIM];           // Σ w*y per (graph, d)
__device__ float  g_den[BATCH * CDIM];           // Σ w   per (graph, d)

// ---------------- K1a: W1 row d -> wcat row 2d (fp16) ----------------
__global__ void k_wcopy(const float* __restrict__ W1) {
    int i = blockIdx.x * 256 + threadIdx.x;      // 262144 elements
    int d = i >> 9, c = i & 511;
    g_wcat[(size_t)(2 * d) * CDIM + c] = __float2half(W1[i]);
}

// ---------------- K1b: bcat interleaved [b1_d ; (W2@b1+b2)_d] ----------------
__global__ void k_bcat(const float* __restrict__ W2, const float* __restrict__ b1,
                       const float* __restrict__ b2) {
    __shared__ float sb1[CDIM];
    int t = threadIdx.x;                          // 512 threads
    sb1[t] = b1[t];
    __syncthreads();
    float acc = b2[t];
    const float* row = W2 + (size_t)t * CDIM;
    for (int j = 0; j < CDIM; j++) acc += row[j] * sb1[j];
    g_bcat[2 * t]     = b1[t];
    g_bcat[2 * t + 1] = acc;
}

// ---------------- K1c: W21 = W2 @ W1 -> wcat rows 2d+1 (fp16) ----------------
// Tiled fp32 SIMT GEMM: 64x64 tile per CTA, grid 8x8, 256 thr, 4x4 per thread.
__global__ void __launch_bounds__(256) k_w21(const float* __restrict__ W2,
                                             const float* __restrict__ W1) {
    __shared__ float sA[32][65];   // sA[j][d] : W2 tile transposed
    __shared__ float sB[32][64];   // sB[j][k] : W1 tile
    int t = threadIdx.x;
    int tx = t & 15, ty = t >> 4;
    int d0 = blockIdx.y * 64, k0 = blockIdx.x * 64;
    float acc[4][4] = {};
    for (int jc = 0; jc < CDIM; jc += 32) {
        // W2 tile: coalesce along j (inner dim of W2 rows)
        for (int i = t; i < 64 * 32; i += 256) {
            int r = i >> 5, j = i & 31;
            sA[j][r] = W2[(size_t)(d0 + r) * CDIM + jc + j];
        }
        // W1 tile: coalesce along k
        for (int i = t; i < 32 * 64; i += 256) {
            int j = i >> 6, c = i & 63;
            sB[j][c] = W1[(size_t)(jc + j) * CDIM + k0 + c];
        }
        __syncthreads();
#pragma unroll
        for (int j = 0; j < 32; j++) {
            float a[4], b[4];
#pragma unroll
            for (int i = 0; i < 4; i++) a[i] = sA[j][ty * 4 + i];
#pragma unroll
            for (int l = 0; l < 4; l++) b[l] = sB[j][tx * 4 + l];
#pragma unroll
            for (int i = 0; i < 4; i++)
#pragma unroll
                for (int l = 0; l < 4; l++) acc[i][l] += a[i] * b[l];
        }
        __syncthreads();
    }
#pragma unroll
    for (int i = 0; i < 4; i++)
#pragma unroll
        for (int l = 0; l < 4; l++)
            g_wcat[(size_t)(2 * (d0 + ty * 4 + i) + 1) * CDIM + k0 + tx * 4 + l] =
                __float2half(acc[i][l]);
}

// ---------------- K1d: zero the accumulation buffers ----------------
__global__ void k_zero() {
    int i = blockIdx.x * 512 + threadIdx.x;      // 65536 threads
    g_num[i] = 0.f;
    g_den[i] = 0.f;
}

// ---------------- K2: LayerNorm (eps=1e-5) -> fp16 ----------------
__global__ void k_ln(const float* __restrict__ hs, const float* __restrict__ gamma,
                     const float* __restrict__ beta) {
    __shared__ float s_sum[4], s_sq[4];
    int row = blockIdx.x;
    int t = threadIdx.x;                          // 128 threads, 4 floats each
    const float4 v = __ldg((const float4*)(hs + (size_t)row * CDIM) + t);
    float s = v.x + v.y + v.z + v.w;
    float q = v.x * v.x + v.y * v.y + v.z * v.z + v.w * v.w;
#pragma unroll
    for (int o = 16; o > 0; o >>= 1) {
        s += __shfl_xor_sync(0xFFFFFFFFu, s, o);
        q += __shfl_xor_sync(0xFFFFFFFFu, q, o);
    }
    if ((t & 31) == 0) { s_sum[t >> 5] = s; s_sq[t >> 5] = q; }
    __syncthreads();
    s = s_sum[0] + s_sum[1] + s_sum[2] + s_sum[3];
    q = s_sq[0] + s_sq[1] + s_sq[2] + s_sq[3];
    float mu = s * (1.f / CDIM);
    float var = q * (1.f / CDIM) - mu * mu;
    float rs = rsqrtf(var + 1e-5f);
    float4 g4 = __ldg((const float4*)gamma + t);
    float4 b4 = __ldg((const float4*)beta + t);
    __half2 h0 = __floats2half2_rn((v.x - mu) * rs * g4.x + b4.x,
                                   (v.y - mu) * rs * g4.y + b4.y);
    __half2 h1 = __floats2half2_rn((v.z - mu) * rs * g4.z + b4.z,
                                   (v.w - mu) * rs * g4.w + b4.w);
    uint2 packed;
    packed.x = *(uint32_t*)&h0;
    packed.y = *(uint32_t*)&h1;
    *((uint2*)(g_x + (size_t)row * CDIM) + t) = packed;
}

// ---------------- K3: GEMM + fused softmax-pool epilogue ----------------
// CTA tile 128 rows x 128 interleaved cols (= 64 distinct features d).
// After the mainloop: w=exp(z+bz), per-row (w*y, w) -> smem, segment-scan over
// sorted data_batch, atomicAdd per-(graph,d) partials into g_num/g_den.
__device__ __forceinline__ uint32_t smem_u32(const void* p) {
    return (uint32_t)__cvta_generic_to_shared(p);
}

#define EPI_STRIDE 68   // floats per smem row in epilogue (64 + 4 pad)

__global__ void __launch_bounds__(256, 2) k_gemm(const int* __restrict__ batch) {
    extern __shared__ __half sm[];
    const int tid = threadIdx.x;
    const int lane = tid & 31, wid = tid >> 5;
    const int n0 = blockIdx.x * 128;           // interleaved col tile (8 tiles)
    const int row0 = blockIdx.y * 128;         // row tile (1024 tiles)
    __half* As[2] = { sm,         sm + 9216 };
    __half* Bs[2] = { sm + 18432, sm + 27648 };

    float acc[2][8][4];
#pragma unroll
    for (int a = 0; a < 2; a++)
#pragma unroll
        for (int b = 0; b < 8; b++)
#pragma unroll
            for (int c = 0; c < 4; c++) acc[a][b][c] = 0.f;

    auto load_chunk = [&](int kc, int bufi) {
        int k0 = kc * 64;
#pragma unroll
        for (int i = 0; i < 4; i++) {
            int sidx = tid + i * 256;
            int r = sidx >> 3, c = sidx & 7;   // 128 rows x 8 16B-chunks
            const __half* ga = g_x + (size_t)(row0 + r) * CDIM + k0 + c * 8;
            uint32_t sa = smem_u32(As[bufi] + r * 72 + c * 8);
            asm volatile("cp.async.cg.shared.global [%0], [%1], 16;\n" :: "r"(sa), "l"(ga));
            const __half* gb = g_wcat + (size_t)(n0 + r) * CDIM + k0 + c * 8;
            uint32_t sb = smem_u32(Bs[bufi] + r * 72 + c * 8);
            asm volatile("cp.async.cg.shared.global [%0], [%1], 16;\n" :: "r"(sb), "l"(gb));
        }
        asm volatile("cp.async.commit_group;\n");
    };

    load_chunk(0, 0);
    int buf = 0;
    const int wm = (wid & 3) * 32;             // 4 warps along M
    const int wn = (wid >> 2) * 64;            // 2 warps along N

    for (int kc = 0; kc < 8; kc++) {
        if (kc < 7) {
            load_chunk(kc + 1, buf ^ 1);
            asm volatile("cp.async.wait_group 1;\n");
        } else {
            asm volatile("cp.async.wait_group 0;\n");
        }
        __syncthreads();
#pragma unroll
        for (int kk = 0; kk < 4; kk++) {
            uint32_t a_r[2][4];
#pragma unroll
            for (int tm = 0; tm < 2; tm++) {
                uint32_t addr = smem_u32(As[buf] + (wm + tm * 16 + (lane & 15)) * 72
                                         + kk * 16 + (lane >> 4) * 8);
                asm volatile("ldmatrix.sync.aligned.m8n8.x4.shared.b16 {%0,%1,%2,%3}, [%4];\n"
                             : "=r"(a_r[tm][0]), "=r"(a_r[tm][1]),
                               "=r"(a_r[tm][2]), "=r"(a_r[tm][3]) : "r"(addr));
            }
            uint32_t b_r[4][4];
#pragma unroll
            for (int bp = 0; bp < 4; bp++) {
                uint32_t addr = smem_u32(Bs[buf] + (wn + bp * 16 + (lane & 7) + ((lane >> 4) << 3)) * 72
                                         + kk * 16 + (((lane >> 3) & 1) << 3));
                asm volatile("ldmatrix.sync.aligned.m8n8.x4.shared.b16 {%0,%1,%2,%3}, [%4];\n"
                             : "=r"(b_r[bp][0]), "=r"(b_r[bp][1]),
                               "=r"(b_r[bp][2]), "=r"(b_r[bp][3]) : "r"(addr));
            }
#pragma unroll
            for (int tm = 0; tm < 2; tm++) {
#pragma unroll
                for (int bp = 0; bp < 4; bp++) {
                    asm volatile("mma.sync.aligned.m16n8k16.row.col.f32.f16.f16.f32 "
                                 "{%0,%1,%2,%3}, {%4,%5,%6,%7}, {%8,%9}, {%0,%1,%2,%3};\n"
                                 : "+f"(acc[tm][bp * 2][0]), "+f"(acc[tm][bp * 2][1]),
                                   "+f"(acc[tm][bp * 2][2]), "+f"(acc[tm][bp * 2][3])
                                 : "r"(a_r[tm][0]), "r"(a_r[tm][1]), "r"(a_r[tm][2]), "r"(a_r[tm][3]),
                                   "r"(b_r[bp][0]), "r"(b_r[bp][1]));
                    asm volatile("mma.sync.aligned.m16n8k16.row.col.f32.f16.f16.f32 "
                                 "{%0,%1,%2,%3}, {%4,%5,%6,%7}, {%8,%9}, {%0,%1,%2,%3};\n"
                                 : "+f"(acc[tm][bp * 2 + 1][0]), "+f"(acc[tm][bp * 2 + 1][1]),
                                   "+f"(acc[tm][bp * 2 + 1][2]), "+f"(acc[tm][bp * 2 + 1][3])
                                 : "r"(a_r[tm][0]), "r"(a_r[tm][1]), "r"(a_r[tm][2]), "r"(a_r[tm][3]),
                                   "r"(b_r[bp][2]), "r"(b_r[bp][3]));
                }
            }
        }
        __syncthreads();
        buf ^= 1;
    }

    // ---------- fused epilogue ----------
    // smem reuse: s_num[128][68], s_den[128][68] fp32, s_batch[128] int.
    float* s_num = (float*)sm;
    float* s_den = s_num + 128 * EPI_STRIDE;
    int*   s_bat = (int*)(s_den + 128 * EPI_STRIDE);

    if (tid < 128) s_bat[tid] = __ldg(&batch[row0 + tid]);

#pragma unroll
    for (int tm = 0; tm < 2; tm++) {
        int r = wm + tm * 16 + (lane >> 2);        // row within tile
#pragma unroll
        for (int j = 0; j < 8; j++) {
            int cl = wn + j * 8 + (lane & 3) * 2;  // interleaved col (even = y)
            int dl = cl >> 1;                      // feature index within tile [0,64)
            float by = __ldg(&g_bcat[n0 + cl]);
            float bz = __ldg(&g_bcat[n0 + cl + 1]);
            // rows r and r+8
            float y0 = acc[tm][j][0] + by;
            float w0 = __expf(acc[tm][j][1] + bz);
            float y1 = acc[tm][j][2] + by;
            float w1 = __expf(acc[tm][j][3] + bz);
            s_num[r * EPI_STRIDE + dl]       = w0 * y0;
            s_den[r * EPI_STRIDE + dl]       = w0;
            s_num[(r + 8) * EPI_STRIDE + dl] = w1 * y1;
            s_den[(r + 8) * EPI_STRIDE + dl] = w1;
        }
    }
    __syncthreads();

    // segment-scan 32 rows per thread: 256 thr = 64 features x 4 row-quarters
    {
        int d = tid & 63;
        int q = tid >> 6;
        int dglob = (n0 >> 1) + d;
        float an = 0.f, ad = 0.f;
        int curb = s_bat[q * 32];
#pragma unroll 4
        for (int r = 0; r < 32; r++) {
            int rr = q * 32 + r;
            int bb = s_bat[rr];
            if (bb != curb) {
                atomicAdd(&g_num[curb * CDIM + dglob], an);
                atomicAdd(&g_den[curb * CDIM + dglob], ad);
                an = 0.f; ad = 0.f; curb = bb;
            }
            an += s_num[rr * EPI_STRIDE + d];
            ad += s_den[rr * EPI_STRIDE + d];
        }
        atomicAdd(&g_num[curb * CDIM + dglob], an);
        atomicAdd(&g_den[curb * CDIM + dglob], ad);
    }
}

// ---------------- K4: finalize out = num / den ----------------
__global__ void k_final(float* __restrict__ out) {
    int i = blockIdx.x * 512 + threadIdx.x;      // 65536 threads
    float den = g_den[i];
    out[i] = (den > 0.f) ? (g_num[i] / den) : 0.f;
}

// ---------------- host launcher ----------------
extern "C" void kernel_launch(void* const* d_in, const int* in_sizes, int n_in,
                              void* d_out, int out_size) {
    const float* hs    = (const float*)d_in[0];
    const int*   batch = (const int*)d_in[1];
    // d_in[2] = max_nodes (unused)
    const float* gamma = (const float*)d_in[3];
    const float* beta  = (const float*)d_in[4];
    const float* W1    = (const float*)d_in[5];
    const float* b1    = (const float*)d_in[6];
    const float* W2    = (const float*)d_in[7];
    const float* b2    = (const float*)d_in[8];
    float* out = (float*)d_out;

    cudaFuncSetAttribute(k_gemm, cudaFuncAttributeMaxDynamicSharedMemorySize, 73728);

    k_wcopy<<<1024, 256>>>(W1);
    k_bcat<<<1, 512>>>(W2, b1, b2);
    dim3 wg(8, 8);
    k_w21<<<wg, 256>>>(W2, W1);
    k_zero<<<128, 512>>>();
    k_ln<<<T_TOT, 128>>>(hs, gamma, beta);
    dim3 gg(8, 1024);
    k_gemm<<<gg, 256, 73728>>>(batch);
    k_final<<<128, 512>>>(out);
}

// round 5
// speedup vs baseline: 1.9394x; 1.6759x over previous
#include <cuda_runtime.h>
#include <cuda_fp16.h>
#include <cstdint>
#include <cstddef>

// Problem constants (fixed by dataset)
#define T_TOT 131072
#define CDIM  512
#define NF    1024   // interleaved [y_0,z_0,y_1,z_1,...]  (y=W1 path, z=W2W1 path)
#define BATCH 128

// Feature dispatch: tcgen05 requires the sm_103a ("arch-accelerated") target.
#if defined(__CUDA_ARCH_FEAT_SM103_ALL)
#define HAS_TC 1
#else
#define HAS_TC 0
#endif

// ---------------- scratch: __device__ globals (no allocation allowed) ----------------
__device__ __half g_x[(size_t)T_TOT * CDIM];     // LN output fp16           134 MB
__device__ __half g_wcat[(size_t)NF * CDIM];     // interleaved weights, K-major (1 MB)
__device__ float  g_bcat[NF];                    // interleaved [b1_d ; (W2 b1 + b2)_d]
__device__ float  g_num[BATCH * CDIM];           // Σ w*y per (graph, d)
__device__ float  g_den[BATCH * CDIM];           // Σ w   per (graph, d)

// ---------------- PTX helpers ----------------
__device__ __forceinline__ uint32_t smem_u32(const void* p) {
    return (uint32_t)__cvta_generic_to_shared(p);
}
#define SWZ128(o) ((o) ^ (((o) >> 3) & 0x70))

// ---------------- K1a: W1 row d -> wcat row 2d (fp16); also zero accumulators -------
__global__ void k_wcopy(const float* __restrict__ W1) {
    int i = blockIdx.x * 256 + threadIdx.x;      // 262144 elements
    int d = i >> 9, c = i & 511;
    g_wcat[(size_t)(2 * d) * CDIM + c] = __float2half(W1[i]);
    if (i < BATCH * CDIM) { g_num[i] = 0.f; g_den[i] = 0.f; }
}

// ---------------- K1b: bcat interleaved [b1_d ; (W2@b1+b2)_d], warp-per-output ------
__global__ void k_bcat(const float* __restrict__ W2, const float* __restrict__ b1,
                       const float* __restrict__ b2) {
    int w = (blockIdx.x * 256 + threadIdx.x) >> 5;   // 0..511 (grid 64 x 256)
    int lane = threadIdx.x & 31;
    float acc = 0.f;
    const float* row = W2 + (size_t)w * CDIM;
#pragma unroll 4
    for (int j = lane; j < CDIM; j += 32) acc += row[j] * __ldg(&b1[j]);
#pragma unroll
    for (int o = 16; o > 0; o >>= 1) acc += __shfl_xor_sync(0xFFFFFFFFu, acc, o);
    if (lane == 0) {
        g_bcat[2 * w]     = __ldg(&b1[w]);
        g_bcat[2 * w + 1] = acc + __ldg(&b2[w]);
    }
}

// ---------------- K1c: W21 = W2 @ W1 -> wcat rows 2d+1 (fp16) ----------------
__global__ void __launch_bounds__(256) k_w21(const float* __restrict__ W2,
                                             const float* __restrict__ W1) {
    __shared__ float sA[32][65];
    __shared__ float sB[32][64];
    int t = threadIdx.x;
    int tx = t & 15, ty = t >> 4;
    int d0 = blockIdx.y * 64, k0 = blockIdx.x * 64;
    float acc[4][4] = {};
    for (int jc = 0; jc < CDIM; jc += 32) {
        for (int i = t; i < 64 * 32; i += 256) {
            int r = i >> 5, j = i & 31;
            sA[j][r] = W2[(size_t)(d0 + r) * CDIM + jc + j];
        }
        for (int i = t; i < 32 * 64; i += 256) {
            int j = i >> 6, c = i & 63;
            sB[j][c] = W1[(size_t)(jc + j) * CDIM + k0 + c];
        }
        __syncthreads();
#pragma unroll
        for (int j = 0; j < 32; j++) {
            float a[4], b[4];
#pragma unroll
            for (int i = 0; i < 4; i++) a[i] = sA[j][ty * 4 + i];
#pragma unroll
            for (int l = 0; l < 4; l++) b[l] = sB[j][tx * 4 + l];
#pragma unroll
            for (int i = 0; i < 4; i++)
#pragma unroll
                for (int l = 0; l < 4; l++) acc[i][l] += a[i] * b[l];
        }
        __syncthreads();
    }
#pragma unroll
    for (int i = 0; i < 4; i++)
#pragma unroll
        for (int l = 0; l < 4; l++)
            g_wcat[(size_t)(2 * (d0 + ty * 4 + i) + 1) * CDIM + k0 + tx * 4 + l] =
                __float2half(acc[i][l]);
}

// ---------------- K2: LayerNorm (eps=1e-5) -> fp16 ----------------
__global__ void k_ln(const float* __restrict__ hs, const float* __restrict__ gamma,
                     const float* __restrict__ beta) {
    __shared__ float s_sum[4], s_sq[4];
    int row = blockIdx.x;
    int t = threadIdx.x;                          // 128 threads, 4 floats each
    const float4 v = __ldg((const float4*)(hs + (size_t)row * CDIM) + t);
    float s = v.x + v.y + v.z + v.w;
    float q = v.x * v.x + v.y * v.y + v.z * v.z + v.w * v.w;
#pragma unroll
    for (int o = 16; o > 0; o >>= 1) {
        s += __shfl_xor_sync(0xFFFFFFFFu, s, o);
        q += __shfl_xor_sync(0xFFFFFFFFu, q, o);
    }
    if ((t & 31) == 0) { s_sum[t >> 5] = s; s_sq[t >> 5] = q; }
    __syncthreads();
    s = s_sum[0] + s_sum[1] + s_sum[2] + s_sum[3];
    q = s_sq[0] + s_sq[1] + s_sq[2] + s_sq[3];
    float mu = s * (1.f / CDIM);
    float var = q * (1.f / CDIM) - mu * mu;
    float rs = rsqrtf(var + 1e-5f);
    float4 g4 = __ldg((const float4*)gamma + t);
    float4 b4 = __ldg((const float4*)beta + t);
    __half2 h0 = __floats2half2_rn((v.x - mu) * rs * g4.x + b4.x,
                                   (v.y - mu) * rs * g4.y + b4.y);
    __half2 h1 = __floats2half2_rn((v.z - mu) * rs * g4.z + b4.z,
                                   (v.w - mu) * rs * g4.w + b4.w);
    uint2 packed;
    packed.x = *(uint32_t*)&h0;
    packed.y = *(uint32_t*)&h1;
    *((uint2*)(g_x + (size_t)row * CDIM) + t) = packed;
}

// ============================================================================
// K3-TC: tcgen05 GEMM + fused epilogue (compiled ONLY for sm_103a targets)
// ============================================================================
#define KCH       64
#define STG_BYTES 65536           // A0 16K | A1 16K | B 32K
#define SM_CTRL   2048
#define SM_TOTAL_TC (SM_CTRL + 3 * STG_BYTES)   // 198656
#define IDESC 0x8400010u          // f16*f16->f32, M=128, N=256 (idesc[16:24)=N/4)

#if HAS_TC
__device__ __forceinline__ uint32_t elect_one_pred() {
    uint32_t pred;
    asm volatile("{\n\t.reg .pred p;\n\telect.sync _|p, 0xFFFFFFFF;\n\tselp.b32 %0, 1, 0, p;\n\t}"
                 : "=r"(pred));
    return pred;
}
static constexpr uint64_t SMEM_DESC_BASE_SW128 =
    (uint64_t(2) << 61) | (uint64_t(1) << 46) | (uint64_t(64) << 32) | (uint64_t(1) << 16);
#define MAKE_SMEM_DESC(b) (SMEM_DESC_BASE_SW128 | ((uint64_t)((b) >> 4) & 0x3FFF))
#define MBARRIER_INIT(a, c) \
    asm volatile("mbarrier.init.shared.b64 [%0], %1;" :: "r"(a), "r"(c) : "memory")
#define MBAR_WAIT(a, ph) do {                                                  \
    asm volatile("{\n\t.reg .pred P1;\n\t"                                     \
        "WL_%=:\n\t"                                                           \
        "mbarrier.try_wait.parity.acquire.cta.shared::cta.b64 P1, [%0], %1, 0x989680;\n\t" \
        "@P1 bra.uni WD_%=;\n\t"                                               \
        "bra.uni WL_%=;\n\t"                                                   \
        "WD_%=:\n\t}" :: "r"(a), "r"(ph) : "memory");                          \
} while (0)
__device__ __forceinline__ void mma_f16_ss(uint32_t d_tmem, uint64_t a_desc, uint64_t b_desc,
                                           uint32_t idesc, uint32_t en) {
    uint32_t z = 0;
    asm volatile(
        "{\n\t.reg .pred p;\n\t"
        "setp.ne.u32 p, %5, 0;\n\t"
        "tcgen05.mma.cta_group::1.kind::f16 [%0], %1, %2, %3, {%4, %4, %4, %4}, p;\n\t"
        "}"
        :: "r"(d_tmem), "l"(a_desc), "l"(b_desc), "r"(idesc), "r"(z), "r"(en)
        : "memory");
}
#define LDTM_X32(r, a) \
    asm volatile( \
        "tcgen05.ld.sync.aligned.32x32b.x32.b32 " \
        "{%0, %1, %2, %3, %4, %5, %6, %7, " \
        " %8, %9, %10, %11, %12, %13, %14, %15, " \
        " %16, %17, %18, %19, %20, %21, %22, %23, " \
        " %24, %25, %26, %27, %28, %29, %30, %31}, [%32];" \
        : "=r"((r)[0]),  "=r"((r)[1]),  "=r"((r)[2]),  "=r"((r)[3]), \
          "=r"((r)[4]),  "=r"((r)[5]),  "=r"((r)[6]),  "=r"((r)[7]), \
          "=r"((r)[8]),  "=r"((r)[9]),  "=r"((r)[10]), "=r"((r)[11]), \
          "=r"((r)[12]), "=r"((r)[13]), "=r"((r)[14]), "=r"((r)[15]), \
          "=r"((r)[16]), "=r"((r)[17]), "=r"((r)[18]), "=r"((r)[19]), \
          "=r"((r)[20]), "=r"((r)[21]), "=r"((r)[22]), "=r"((r)[23]), \
          "=r"((r)[24]), "=r"((r)[25]), "=r"((r)[26]), "=r"((r)[27]), \
          "=r"((r)[28]), "=r"((r)[29]), "=r"((r)[30]), "=r"((r)[31]) \
        : "r"(a))
#endif // HAS_TC

__global__ void __launch_bounds__(256, 1) k_gemm_tc(const int* __restrict__ batch) {
#if HAS_TC
    extern __shared__ char sm[];
    const uint32_t smb = smem_u32(sm);
    const int tid = threadIdx.x;
    const int lane = tid & 31, wid = tid >> 5;
    const int n0 = blockIdx.x * 256;
    const int row0 = blockIdx.y * 256;
    int* s_bat = (int*)(sm + 1024);

    if (wid == 0)
        asm volatile("tcgen05.alloc.cta_group::1.sync.aligned.shared::cta.b32 [%0], %1;"
                     :: "r"(smb), "r"(512) : "memory");
    if (tid == 0) {
        MBARRIER_INIT(smb + 8, 1);
        MBARRIER_INIT(smb + 16, 1);
        MBARRIER_INIT(smb + 24, 1);
    }
    s_bat[tid] = __ldg(&batch[row0 + tid]);
    __syncthreads();
    uint32_t tmem;
    asm volatile("ld.shared.b32 %0, [%1];" : "=r"(tmem) : "r"(smb));

    auto load_chunk = [&](int c, int s) {
        const int k0 = c * KCH;
        const uint32_t stg = smb + SM_CTRL + s * STG_BYTES;
#pragma unroll
        for (int i = 0; i < 8; i++) {
            int gidx = tid + i * 256;
            int r = gidx >> 3, cc = gidx & 7;
            const __half* ga = g_x + (size_t)(row0 + r) * CDIM + k0 + cc * 8;
            uint32_t off = (r < 128) ? SWZ128(r * 128 + cc * 16)
                                     : (16384u + SWZ128((r - 128) * 128 + cc * 16));
            asm volatile("cp.async.cg.shared.global [%0], [%1], 16;\n" :: "r"(stg + off), "l"(ga));
            const __half* gb = g_wcat + (size_t)(n0 + r) * CDIM + k0 + cc * 8;
            asm volatile("cp.async.cg.shared.global [%0], [%1], 16;\n"
                         :: "r"(stg + 32768u + SWZ128(r * 128 + cc * 16)), "l"(gb));
        }
        asm volatile("cp.async.commit_group;\n" ::: "memory");
    };

    load_chunk(0, 0);
    load_chunk(1, 1);
    load_chunk(2, 2);

    for (int c = 0; c < 8; c++) {
        const int s = c % 3;
        if (c <= 5)      asm volatile("cp.async.wait_group 2;\n" ::: "memory");
        else if (c == 6) asm volatile("cp.async.wait_group 1;\n" ::: "memory");
        else             asm volatile("cp.async.wait_group 0;\n" ::: "memory");
        __syncthreads();
        if (wid == 0) {
            if (elect_one_pred()) {
                asm volatile("fence.proxy.async.shared::cta;" ::: "memory");
                const uint32_t stg = smb + SM_CTRL + s * STG_BYTES;
                uint64_t dA0 = MAKE_SMEM_DESC(stg);
                uint64_t dA1 = MAKE_SMEM_DESC(stg + 16384u);
                uint64_t dB  = MAKE_SMEM_DESC(stg + 32768u);
#pragma unroll
                for (int ks = 0; ks < 4; ks++) {
                    uint32_t en = (c > 0 || ks > 0) ? 1u : 0u;
                    mma_f16_ss(tmem,       dA0 + ks * 2, dB + ks * 2, IDESC, en);
                    mma_f16_ss(tmem + 256, dA1 + ks * 2, dB + ks * 2, IDESC, en);
                }
                asm volatile("tcgen05.commit.cta_group::1.mbarrier::arrive::one.shared::cluster.b64 [%0];"
                             :: "r"(smb + 8 + s * 8) : "memory");
            }
        }
        if (c + 3 < 8) {
            MBAR_WAIT(smb + 8 + s * 8, (c / 3) & 1);
            load_chunk(c + 3, s);
        }
    }
    MBAR_WAIT(smb + 16, 0);
    asm volatile("tcgen05.fence::after_thread_sync;" ::: "memory");
    __syncthreads();

    float* s_num = (float*)(sm + SM_CTRL);
    float* s_den = s_num + 256 * 33;
    const int wg = wid >> 2;
    const uint32_t wgcol = wg ? 256u : 0u;
    const int rloc = wg * 128 + (wid & 3) * 32 + lane;
    const int dscan = tid & 31, gscan = tid >> 5;

#pragma unroll 1
    for (int f0 = 0; f0 < 128; f0 += 32) {
        uint32_t rr[64];
        LDTM_X32(rr,      tmem + wgcol + 2 * f0);
        LDTM_X32(rr + 32, tmem + wgcol + 2 * f0 + 32);
        asm volatile("tcgen05.wait::ld.sync.aligned;" ::: "memory");
#pragma unroll
        for (int i = 0; i < 32; i++) {
            float y = __uint_as_float(rr[2 * i])     + __ldg(&g_bcat[n0 + 2 * (f0 + i)]);
            float z = __uint_as_float(rr[2 * i + 1]) + __ldg(&g_bcat[n0 + 2 * (f0 + i) + 1]);
            float w = __expf(z);
            s_num[rloc * 33 + i] = w * y;
            s_den[rloc * 33 + i] = w;
        }
        __syncthreads();
        {
            int dglob = (n0 >> 1) + f0 + dscan;
            float an = 0.f, ad = 0.f;
            int curb = s_bat[gscan * 32];
#pragma unroll 4
            for (int r = 0; r < 32; r++) {
                int rr2 = gscan * 32 + r;
                int bb = s_bat[rr2];
                if (bb != curb) {
                    atomicAdd(&g_num[curb * CDIM + dglob], an);
                    atomicAdd(&g_den[curb * CDIM + dglob], ad);
                    an = 0.f; ad = 0.f; curb = bb;
                }
                an += s_num[rr2 * 33 + dscan];
                ad += s_den[rr2 * 33 + dscan];
            }
            atomicAdd(&g_num[curb * CDIM + dglob], an);
            atomicAdd(&g_den[curb * CDIM + dglob], ad);
        }
        __syncthreads();
    }
    if (wid == 0)
        asm volatile("tcgen05.dealloc.cta_group::1.sync.aligned.b32 %0, %1;" :: "r"(tmem), "r"(512));
#endif // HAS_TC
}

// ============================================================================
// K3-MMA: legacy mma.sync GEMM + fused epilogue (compiled for plain sm_103)
// ============================================================================
#define EPI_STRIDE 68
#define SM_TOTAL_MMA 73728

__global__ void __launch_bounds__(256, 2) k_gemm_mma(const int* __restrict__ batch) {
#if !HAS_TC
    extern __shared__ __half smh[];
    const int tid = threadIdx.x;
    const int lane = tid & 31, wid = tid >> 5;
    const int n0 = blockIdx.x * 128;
    const int row0 = blockIdx.y * 128;
    __half* As[2] = { smh,         smh + 9216 };
    __half* Bs[2] = { smh + 18432, smh + 27648 };

    float acc[2][8][4];
#pragma unroll
    for (int a = 0; a < 2; a++)
#pragma unroll
        for (int b = 0; b < 8; b++)
#pragma unroll
            for (int c = 0; c < 4; c++) acc[a][b][c] = 0.f;

    auto load_chunk = [&](int kc, int bufi) {
        int k0 = kc * 64;
#pragma unroll
        for (int i = 0; i < 4; i++) {
            int sidx = tid + i * 256;
            int r = sidx >> 3, c = sidx & 7;
            const __half* ga = g_x + (size_t)(row0 + r) * CDIM + k0 + c * 8;
            uint32_t sa = smem_u32(As[bufi] + r * 72 + c * 8);
            asm volatile("cp.async.cg.shared.global [%0], [%1], 16;\n" :: "r"(sa), "l"(ga));
            const __half* gb = g_wcat + (size_t)(n0 + r) * CDIM + k0 + c * 8;
            uint32_t sb = smem_u32(Bs[bufi] + r * 72 + c * 8);
            asm volatile("cp.async.cg.shared.global [%0], [%1], 16;\n" :: "r"(sb), "l"(gb));
        }
        asm volatile("cp.async.commit_group;\n");
    };

    load_chunk(0, 0);
    int buf = 0;
    const int wm = (wid & 3) * 32;
    const int wn = (wid >> 2) * 64;

    for (int kc = 0; kc < 8; kc++) {
        if (kc < 7) {
            load_chunk(kc + 1, buf ^ 1);
            asm volatile("cp.async.wait_group 1;\n");
        } else {
            asm volatile("cp.async.wait_group 0;\n");
        }
        __syncthreads();
#pragma unroll
        for (int kk = 0; kk < 4; kk++) {
            uint32_t a_r[2][4];
#pragma unroll
            for (int tm = 0; tm < 2; tm++) {
                uint32_t addr = smem_u32(As[buf] + (wm + tm * 16 + (lane & 15)) * 72
                                         + kk * 16 + (lane >> 4) * 8);
                asm volatile("ldmatrix.sync.aligned.m8n8.x4.shared.b16 {%0,%1,%2,%3}, [%4];\n"
                             : "=r"(a_r[tm][0]), "=r"(a_r[tm][1]),
                               "=r"(a_r[tm][2]), "=r"(a_r[tm][3]) : "r"(addr));
            }
            uint32_t b_r[4][4];
#pragma unroll
            for (int bp = 0; bp < 4; bp++) {
                uint32_t addr = smem_u32(Bs[buf] + (wn + bp * 16 + (lane & 7) + ((lane >> 4) << 3)) * 72
                                         + kk * 16 + (((lane >> 3) & 1) << 3));
                asm volatile("ldmatrix.sync.aligned.m8n8.x4.shared.b16 {%0,%1,%2,%3}, [%4];\n"
                             : "=r"(b_r[bp][0]), "=r"(b_r[bp][1]),
                               "=r"(b_r[bp][2]), "=r"(b_r[bp][3]) : "r"(addr));
            }
#pragma unroll
            for (int tm = 0; tm < 2; tm++) {
#pragma unroll
                for (int bp = 0; bp < 4; bp++) {
                    asm volatile("mma.sync.aligned.m16n8k16.row.col.f32.f16.f16.f32 "
                                 "{%0,%1,%2,%3}, {%4,%5,%6,%7}, {%8,%9}, {%0,%1,%2,%3};\n"
                                 : "+f"(acc[tm][bp * 2][0]), "+f"(acc[tm][bp * 2][1]),
                                   "+f"(acc[tm][bp * 2][2]), "+f"(acc[tm][bp * 2][3])
                                 : "r"(a_r[tm][0]), "r"(a_r[tm][1]), "r"(a_r[tm][2]), "r"(a_r[tm][3]),
                                   "r"(b_r[bp][0]), "r"(b_r[bp][1]));
                    asm volatile("mma.sync.aligned.m16n8k16.row.col.f32.f16.f16.f32 "
                                 "{%0,%1,%2,%3}, {%4,%5,%6,%7}, {%8,%9}, {%0,%1,%2,%3};\n"
                                 : "+f"(acc[tm][bp * 2 + 1][0]), "+f"(acc[tm][bp * 2 + 1][1]),
                                   "+f"(acc[tm][bp * 2 + 1][2]), "+f"(acc[tm][bp * 2 + 1][3])
                                 : "r"(a_r[tm][0]), "r"(a_r[tm][1]), "r"(a_r[tm][2]), "r"(a_r[tm][3]),
                                   "r"(b_r[bp][2]), "r"(b_r[bp][3]));
                }
            }
        }
        __syncthreads();
        buf ^= 1;
    }

    float* s_num = (float*)smh;
    float* s_den = s_num + 128 * EPI_STRIDE;
    int*   s_bat = (int*)(s_den + 128 * EPI_STRIDE);

    if (tid < 128) s_bat[tid] = __ldg(&batch[row0 + tid]);

#pragma unroll
    for (int tm = 0; tm < 2; tm++) {
        int r = wm + tm * 16 + (lane >> 2);
#pragma unroll
        for (int j = 0; j < 8; j++) {
            int cl = wn + j * 8 + (lane & 3) * 2;
            int dl = cl >> 1;
            float by = __ldg(&g_bcat[n0 + cl]);
            float bz = __ldg(&g_bcat[n0 + cl + 1]);
            float y0 = acc[tm][j][0] + by;
            float w0 = __expf(acc[tm][j][1] + bz);
            float y1 = acc[tm][j][2] + by;
            float w1 = __expf(acc[tm][j][3] + bz);
            s_num[r * EPI_STRIDE + dl]       = w0 * y0;
            s_den[r * EPI_STRIDE + dl]       = w0;
            s_num[(r + 8) * EPI_STRIDE + dl] = w1 * y1;
            s_den[(r + 8) * EPI_STRIDE + dl] = w1;
        }
    }
    __syncthreads();

    {
        int d = tid & 63;
        int q = tid >> 6;
        int dglob = (n0 >> 1) + d;
        float an = 0.f, ad = 0.f;
        int curb = s_bat[q * 32];
#pragma unroll 4
        for (int r = 0; r < 32; r++) {
            int rr = q * 32 + r;
            int bb = s_bat[rr];
            if (bb != curb) {
                atomicAdd(&g_num[curb * CDIM + dglob], an);
                atomicAdd(&g_den[curb * CDIM + dglob], ad);
                an = 0.f; ad = 0.f; curb = bb;
            }
            an += s_num[rr * EPI_STRIDE + d];
            ad += s_den[rr * EPI_STRIDE + d];
        }
        atomicAdd(&g_num[curb * CDIM + dglob], an);
        atomicAdd(&g_den[curb * CDIM + dglob], ad);
    }
#endif // !HAS_TC
}

// ---------------- K4: finalize out = num / den ----------------
__global__ void k_final(float* __restrict__ out) {
    int i = blockIdx.x * 512 + threadIdx.x;
    float den = g_den[i];
    out[i] = (den > 0.f) ? (g_num[i] / den) : 0.f;
}

// ---------------- host launcher ----------------
extern "C" void kernel_launch(void* const* d_in, const int* in_sizes, int n_in,
                              void* d_out, int out_size) {
    const float* hs    = (const float*)d_in[0];
    const int*   batch = (const int*)d_in[1];
    // d_in[2] = max_nodes (unused)
    const float* gamma = (const float*)d_in[3];
    const float* beta  = (const float*)d_in[4];
    const float* W1    = (const float*)d_in[5];
    const float* b1    = (const float*)d_in[6];
    const float* W2    = (const float*)d_in[7];
    const float* b2    = (const float*)d_in[8];
    float* out = (float*)d_out;

    cudaFuncSetAttribute(k_gemm_tc,  cudaFuncAttributeMaxDynamicSharedMemorySize, SM_TOTAL_TC);
    cudaFuncSetAttribute(k_gemm_mma, cudaFuncAttributeMaxDynamicSharedMemorySize, SM_TOTAL_MMA);

    k_wcopy<<<1024, 256>>>(W1);
    k_bcat<<<64, 256>>>(W2, b1, b2);
    dim3 wg(8, 8);
    k_w21<<<wg, 256>>>(W2, W1);
    k_ln<<<T_TOT, 128>>>(hs, gamma, beta);
    // Exactly one of these has a body in the compiled arch variant.
    dim3 gtc(4, 512);
    k_gemm_tc<<<gtc, 256, SM_TOTAL_TC>>>(batch);
    dim3 gmm(8, 1024);
    k_gemm_mma<<<gmm, 256, SM_TOTAL_MMA>>>(batch);
    k_final<<<128, 512>>>(out);
}

// round 6
// speedup vs baseline: 2.1056x; 1.0857x over previous
#include <cuda_runtime.h>
#include <cuda_fp16.h>
#include <cstdint>
#include <cstddef>

// Problem constants (fixed by dataset)
#define T_TOT 131072
#define CDIM  512
#define NF    1024   // interleaved [y_0,z_0,y_1,z_1,...]  (y=W1 path, z=W2W1 path)
#define BATCH 128

// tcgen05 requires the sm_103a ("arch-accelerated") target pass.
#if defined(__CUDA_ARCH_FEAT_SM103_ALL)
#define HAS_TC 1
#else
#define HAS_TC 0
#endif

// ---------------- scratch: __device__ globals (no allocation allowed) ----------------
// g_x / g_wcat are stored in TILED + PRE-SWIZZLED layout: 32 KB blocks that are
// byte-for-byte the smem image a GEMM stage wants, so cp.async.bulk can copy them.
// A block (row-tile R of 256 rows, K-chunk c of 64 cols):
//   base = (R*8 + c)*32768;  [sub 128-row half][SWZ128(rloc*128 + kloc*2)]
// B block (icol-tile nt of 256, K-chunk c): base = (nt*8 + c)*32768; SWZ128(rloc*128+kloc*2)
__device__ __half g_x[(size_t)T_TOT * CDIM];     // LN output fp16, tiled    134 MB
__device__ __half g_wcat[(size_t)NF * CDIM];     // interleaved weights, tiled (1 MB)
__device__ float  g_bcat[NF];                    // interleaved [b1_d ; (W2 b1 + b2)_d]
__device__ float  g_num[BATCH * CDIM];           // Σ w*y per (graph, d)
__device__ float  g_den[BATCH * CDIM];           // Σ w   per (graph, d)

// ---------------- PTX helpers ----------------
__device__ __forceinline__ uint32_t smem_u32(const void* p) {
    return (uint32_t)__cvta_generic_to_shared(p);
}
#define SWZ128(o) ((o) ^ (((o) >> 3) & 0x70))

// ---------------- K1a: W1 row d -> wcat icol 2d (fp16, tiled); zero accumulators ----
__global__ void k_wcopy(const float* __restrict__ W1) {
    int i = blockIdx.x * 256 + threadIdx.x;      // 262144 elements
    int d = i >> 9, k = i & 511;
    int icol = 2 * d;
    int nt = icol >> 8, rloc = icol & 255;
    int c = k >> 6, klocb = (k & 63) * 2;
    size_t base = ((size_t)(nt * 8 + c)) * 32768;
    uint32_t off = SWZ128((uint32_t)(rloc * 128 + klocb));
    *(__half*)((char*)g_wcat + base + off) = __float2half(W1[i]);
    if (i < BATCH * CDIM) { g_num[i] = 0.f; g_den[i] = 0.f; }
}

// ---------------- K1b: bcat interleaved [b1_d ; (W2@b1+b2)_d], warp-per-output ------
__global__ void k_bcat(const float* __restrict__ W2, const float* __restrict__ b1,
                       const float* __restrict__ b2) {
    int w = (blockIdx.x * 256 + threadIdx.x) >> 5;   // 0..511 (grid 64 x 256)
    int lane = threadIdx.x & 31;
    float acc = 0.f;
    const float* row = W2 + (size_t)w * CDIM;
#pragma unroll 4
    for (int j = lane; j < CDIM; j += 32) acc += row[j] * __ldg(&b1[j]);
#pragma unroll
    for (int o = 16; o > 0; o >>= 1) acc += __shfl_xor_sync(0xFFFFFFFFu, acc, o);
    if (lane == 0) {
        g_bcat[2 * w]     = __ldg(&b1[w]);
        g_bcat[2 * w + 1] = acc + __ldg(&b2[w]);
    }
}

// ---------------- K1c: W21 = W2 @ W1 -> wcat icol 2d+1 (fp16, tiled) ----------------
__global__ void __launch_bounds__(256) k_w21(const float* __restrict__ W2,
                                             const float* __restrict__ W1) {
    __shared__ float sA[32][65];
    __shared__ float sB[32][64];
    int t = threadIdx.x;
    int tx = t & 15, ty = t >> 4;
    int d0 = blockIdx.y * 64, k0 = blockIdx.x * 64;
    float acc[4][4] = {};
    for (int jc = 0; jc < CDIM; jc += 32) {
        for (int i = t; i < 64 * 32; i += 256) {
            int r = i >> 5, j = i & 31;
            sA[j][r] = W2[(size_t)(d0 + r) * CDIM + jc + j];
        }
        for (int i = t; i < 32 * 64; i += 256) {
            int j = i >> 6, c = i & 63;
            sB[j][c] = W1[(size_t)(jc + j) * CDIM + k0 + c];
        }
        __syncthreads();
#pragma unroll
        for (int j = 0; j < 32; j++) {
            float a[4], b[4];
#pragma unroll
            for (int i = 0; i < 4; i++) a[i] = sA[j][ty * 4 + i];
#pragma unroll
            for (int l = 0; l < 4; l++) b[l] = sB[j][tx * 4 + l];
#pragma unroll
            for (int i = 0; i < 4; i++)
#pragma unroll
                for (int l = 0; l < 4; l++) acc[i][l] += a[i] * b[l];
        }
        __syncthreads();
    }
#pragma unroll
    for (int i = 0; i < 4; i++)
#pragma unroll
        for (int l = 0; l < 4; l++) {
            int dr = d0 + ty * 4 + i;
            int k  = k0 + tx * 4 + l;
            int icol = 2 * dr + 1;
            int nt = icol >> 8, rloc = icol & 255;
            int c = k >> 6, klocb = (k & 63) * 2;
            size_t base = ((size_t)(nt * 8 + c)) * 32768;
            uint32_t off = SWZ128((uint32_t)(rloc * 128 + klocb));
            *(__half*)((char*)g_wcat + base + off) = __float2half(acc[i][l]);
        }
}

// ---------------- K2: LayerNorm (eps=1e-5) -> fp16 (tiled + pre-swizzled) -----------
__global__ void k_ln(const float* __restrict__ hs, const float* __restrict__ gamma,
                     const float* __restrict__ beta) {
    __shared__ float s_sum[4], s_sq[4];
    int row = blockIdx.x;
    int t = threadIdx.x;                          // 128 threads, 4 floats each
    const float4 v = __ldg((const float4*)(hs + (size_t)row * CDIM) + t);
    float s = v.x + v.y + v.z + v.w;
    float q = v.x * v.x + v.y * v.y + v.z * v.z + v.w * v.w;
#pragma unroll
    for (int o = 16; o > 0; o >>= 1) {
        s += __shfl_xor_sync(0xFFFFFFFFu, s, o);
        q += __shfl_xor_sync(0xFFFFFFFFu, q, o);
    }
    if ((t & 31) == 0) { s_sum[t >> 5] = s; s_sq[t >> 5] = q; }
    __syncthreads();
    s = s_sum[0] + s_sum[1] + s_sum[2] + s_sum[3];
    q = s_sq[0] + s_sq[1] + s_sq[2] + s_sq[3];
    float mu = s * (1.f / CDIM);
    float var = q * (1.f / CDIM) - mu * mu;
    float rs = rsqrtf(var + 1e-5f);
    float4 g4 = __ldg((const float4*)gamma + t);
    float4 b4 = __ldg((const float4*)beta + t);
    __half2 h0 = __floats2half2_rn((v.x - mu) * rs * g4.x + b4.x,
                                   (v.y - mu) * rs * g4.y + b4.y);
    __half2 h1 = __floats2half2_rn((v.z - mu) * rs * g4.z + b4.z,
                                   (v.w - mu) * rs * g4.w + b4.w);
    uint2 packed;
    packed.x = *(uint32_t*)&h0;
    packed.y = *(uint32_t*)&h1;
    // tiled-swizzled destination: row-tile R, sub-half, K-chunk c
    int R = row >> 8, sub = (row >> 7) & 1, rloc = row & 127;
    int c = t >> 4;                     // byte col 8t -> chunk (8t)/128
    int klocb = (8 * t) & 127;
    size_t base = ((size_t)(R * 8 + c)) * 32768 + (size_t)sub * 16384;
    uint32_t off = SWZ128((uint32_t)(rloc * 128 + klocb));
    *(uint2*)((char*)g_x + base + off) = packed;
}

// ============================================================================
// K3: tcgen05 GEMM + fused softmax-pool epilogue (sm_103a pass only)
// CTA tile M=256 x N=256 icols; grid (4 nt, 512 R). 3-stage bulk-copy pipeline,
// single-warp producer+consumer, mbarrier full/empty per stage.
// ============================================================================
#define STG_BYTES 65536           // A 32K (two 128-row halves) | B 32K
#define SM_CTRL   2048
#define SM_TOTAL_TC (SM_CTRL + 3 * STG_BYTES)   // 198656
#define IDESC 0x8400010u          // f16*f16->f32, M=128, N=256

#if HAS_TC
__device__ __forceinline__ uint32_t elect_one_pred() {
    uint32_t pred;
    asm volatile("{\n\t.reg .pred p;\n\telect.sync _|p, 0xFFFFFFFF;\n\tselp.b32 %0, 1, 0, p;\n\t}"
                 : "=r"(pred));
    return pred;
}
static constexpr uint64_t SMEM_DESC_BASE_SW128 =
    (uint64_t(2) << 61) | (uint64_t(1) << 46) | (uint64_t(64) << 32) | (uint64_t(1) << 16);
#define MAKE_SMEM_DESC(b) (SMEM_DESC_BASE_SW128 | ((uint64_t)((b) >> 4) & 0x3FFF))
#define MBARRIER_INIT(a, c) \
    asm volatile("mbarrier.init.shared.b64 [%0], %1;" :: "r"(a), "r"(c) : "memory")
#define MBAR_EXPECT_TX(a, n) \
    asm volatile("mbarrier.arrive.expect_tx.shared.b64 _, [%0], %1;" :: "r"(a), "r"(n) : "memory")
#define MBAR_WAIT(a, ph) do {                                                  \
    asm volatile("{\n\t.reg .pred P1;\n\t"                                     \
        "WL_%=:\n\t"                                                           \
        "mbarrier.try_wait.parity.acquire.cta.shared::cta.b64 P1, [%0], %1, 0x989680;\n\t" \
        "@P1 bra.uni WD_%=;\n\t"                                               \
        "bra.uni WL_%=;\n\t"                                                   \
        "WD_%=:\n\t}" :: "r"(a), "r"(ph) : "memory");                          \
} while (0)
#define BULK_CP(dst, src, n, mbar) \
    asm volatile("cp.async.bulk.shared::cta.global.mbarrier::complete_tx::bytes " \
                 "[%0], [%1], %2, [%3];" \
                 :: "r"(dst), "l"(src), "r"(n), "r"(mbar) : "memory")
__device__ __forceinline__ void mma_f16_ss(uint32_t d_tmem, uint64_t a_desc, uint64_t b_desc,
                                           uint32_t idesc, uint32_t en) {
    uint32_t z = 0;
    asm volatile(
        "{\n\t.reg .pred p;\n\t"
        "setp.ne.u32 p, %5, 0;\n\t"
        "tcgen05.mma.cta_group::1.kind::f16 [%0], %1, %2, %3, {%4, %4, %4, %4}, p;\n\t"
        "}"
        :: "r"(d_tmem), "l"(a_desc), "l"(b_desc), "r"(idesc), "r"(z), "r"(en)
        : "memory");
}
#define LDTM_X32(r, a) \
    asm volatile( \
        "tcgen05.ld.sync.aligned.32x32b.x32.b32 " \
        "{%0, %1, %2, %3, %4, %5, %6, %7, " \
        " %8, %9, %10, %11, %12, %13, %14, %15, " \
        " %16, %17, %18, %19, %20, %21, %22, %23, " \
        " %24, %25, %26, %27, %28, %29, %30, %31}, [%32];" \
        : "=r"((r)[0]),  "=r"((r)[1]),  "=r"((r)[2]),  "=r"((r)[3]), \
          "=r"((r)[4]),  "=r"((r)[5]),  "=r"((r)[6]),  "=r"((r)[7]), \
          "=r"((r)[8]),  "=r"((r)[9]),  "=r"((r)[10]), "=r"((r)[11]), \
          "=r"((r)[12]), "=r"((r)[13]), "=r"((r)[14]), "=r"((r)[15]), \
          "=r"((r)[16]), "=r"((r)[17]), "=r"((r)[18]), "=r"((r)[19]), \
          "=r"((r)[20]), "=r"((r)[21]), "=r"((r)[22]), "=r"((r)[23]), \
          "=r"((r)[24]), "=r"((r)[25]), "=r"((r)[26]), "=r"((r)[27]), \
          "=r"((r)[28]), "=r"((r)[29]), "=r"((r)[30]), "=r"((r)[31]) \
        : "r"(a))
#endif // HAS_TC

__global__ void __launch_bounds__(256, 1) k_gemm_tc(const int* __restrict__ batch) {
#if HAS_TC
    extern __shared__ char sm[];
    const uint32_t smb = smem_u32(sm);
    const int tid = threadIdx.x;
    const int lane = tid & 31, wid = tid >> 5;
    const int nt = blockIdx.x;                 // icol tile (0..3)
    const int Rt = blockIdx.y;                 // row tile (0..511)
    const int n0 = nt * 256;
    const int row0 = Rt * 256;
    int* s_bat = (int*)(sm + 1024);

    // mbar layout: full[s] at smb+8+s*8, empty[s] at smb+32+s*8
    if (wid == 0)
        asm volatile("tcgen05.alloc.cta_group::1.sync.aligned.shared::cta.b32 [%0], %1;"
                     :: "r"(smb), "r"(512) : "memory");
    if (tid == 0) {
#pragma unroll
        for (int s = 0; s < 3; s++) {
            MBARRIER_INIT(smb + 8 + s * 8, 1);
            MBARRIER_INIT(smb + 32 + s * 8, 1);
        }
    }
    s_bat[tid] = __ldg(&batch[row0 + tid]);
    __syncthreads();
    uint32_t tmem;
    asm volatile("ld.shared.b32 %0, [%1];" : "=r"(tmem) : "r"(smb));

    if (wid == 0) {
        const char* Abase = (const char*)g_x    + (size_t)Rt * 8 * 32768;
        const char* Bbase = (const char*)g_wcat + (size_t)nt * 8 * 32768;
        const uint32_t ep = elect_one_pred();

        auto issue_load = [&](int c, int s) {
            const uint32_t stg = smb + SM_CTRL + s * STG_BYTES;
            const uint32_t fm = smb + 8 + s * 8;
            MBAR_EXPECT_TX(fm, 65536u);
            BULK_CP(stg,          Abase + (size_t)c * 32768, 32768u, fm);
            BULK_CP(stg + 32768u, Bbase + (size_t)c * 32768, 32768u, fm);
        };

        if (ep) { issue_load(0, 0); issue_load(1, 1); issue_load(2, 2); }

        for (int c = 0; c < 8; c++) {
            const int s = c % 3;
            const int ph = (c / 3) & 1;
            MBAR_WAIT(smb + 8 + s * 8, ph);        // data ready
            if (ep) {
                const uint32_t stg = smb + SM_CTRL + s * STG_BYTES;
                uint64_t dA0 = MAKE_SMEM_DESC(stg);
                uint64_t dA1 = MAKE_SMEM_DESC(stg + 16384u);
                uint64_t dB  = MAKE_SMEM_DESC(stg + 32768u);
#pragma unroll
                for (int ks = 0; ks < 4; ks++) {
                    uint32_t en = (c > 0 || ks > 0) ? 1u : 0u;
                    mma_f16_ss(tmem,       dA0 + ks * 2, dB + ks * 2, IDESC, en);
                    mma_f16_ss(tmem + 256, dA1 + ks * 2, dB + ks * 2, IDESC, en);
                }
                asm volatile("tcgen05.commit.cta_group::1.mbarrier::arrive::one.shared::cluster.b64 [%0];"
                             :: "r"(smb + 32 + s * 8) : "memory");
            }
            if (c + 3 < 8) {
                MBAR_WAIT(smb + 32 + s * 8, ph);   // MMA(c) done with stage s
                if (ep) issue_load(c + 3, s);
            }
        }
        // all MMAs complete: last commits on each stage
        MBAR_WAIT(smb + 32 + 0 * 8, 0);            // stage0 commit #3 (c=6)
        MBAR_WAIT(smb + 32 + 1 * 8, 0);            // stage1 commit #3 (c=7)
        MBAR_WAIT(smb + 32 + 2 * 8, 1);            // stage2 commit #2 (c=5)
    }
    __syncthreads();
    asm volatile("tcgen05.fence::after_thread_sync;" ::: "memory");

    // ---- fused epilogue (validated in R5) ----
    float* s_num = (float*)(sm + SM_CTRL);
    float* s_den = s_num + 256 * 33;
    const int wg = wid >> 2;
    const uint32_t wgcol = wg ? 256u : 0u;
    const int rloc = wg * 128 + (wid & 3) * 32 + lane;
    const int dscan = tid & 31, gscan = tid >> 5;

#pragma unroll 1
    for (int f0 = 0; f0 < 128; f0 += 32) {
        uint32_t rr[64];
        LDTM_X32(rr,      tmem + wgcol + 2 * f0);
        LDTM_X32(rr + 32, tmem + wgcol + 2 * f0 + 32);
        asm volatile("tcgen05.wait::ld.sync.aligned;" ::: "memory");
#pragma unroll
        for (int i = 0; i < 32; i++) {
            float y = __uint_as_float(rr[2 * i])     + __ldg(&g_bcat[n0 + 2 * (f0 + i)]);
            float z = __uint_as_float(rr[2 * i + 1]) + __ldg(&g_bcat[n0 + 2 * (f0 + i) + 1]);
            float w = __expf(z);
            s_num[rloc * 33 + i] = w * y;
            s_den[rloc * 33 + i] = w;
        }
        __syncthreads();
        {
            int dglob = (n0 >> 1) + f0 + dscan;
            float an = 0.f, ad = 0.f;
            int curb = s_bat[gscan * 32];
#pragma unroll 4
            for (int r = 0; r < 32; r++) {
                int rr2 = gscan * 32 + r;
                int bb = s_bat[rr2];
                if (bb != curb) {
                    atomicAdd(&g_num[curb * CDIM + dglob], an);
                    atomicAdd(&g_den[curb * CDIM + dglob], ad);
                    an = 0.f; ad = 0.f; curb = bb;
                }
                an += s_num[rr2 * 33 + dscan];
                ad += s_den[rr2 * 33 + dscan];
            }
            atomicAdd(&g_num[curb * CDIM + dglob], an);
            atomicAdd(&g_den[curb * CDIM + dglob], ad);
        }
        __syncthreads();
    }
    if (wid == 0)
        asm volatile("tcgen05.dealloc.cta_group::1.sync.aligned.b32 %0, %1;" :: "r"(tmem), "r"(512));
#endif // HAS_TC
}

// ---------------- K4: finalize out = num / den ----------------
__global__ void k_final(float* __restrict__ out) {
    int i = blockIdx.x * 512 + threadIdx.x;
    float den = g_den[i];
    out[i] = (den > 0.f) ? (g_num[i] / den) : 0.f;
}

// ---------------- host launcher ----------------
extern "C" void kernel_launch(void* const* d_in, const int* in_sizes, int n_in,
                              void* d_out, int out_size) {
    const float* hs    = (const float*)d_in[0];
    const int*   batch = (const int*)d_in[1];
    // d_in[2] = max_nodes (unused)
    const float* gamma = (const float*)d_in[3];
    const float* beta  = (const float*)d_in[4];
    const float* W1    = (const float*)d_in[5];
    const float* b1    = (const float*)d_in[6];
    const float* W2    = (const float*)d_in[7];
    const float* b2    = (const float*)d_in[8];
    float* out = (float*)d_out;

    cudaFuncSetAttribute(k_gemm_tc, cudaFuncAttributeMaxDynamicSharedMemorySize, SM_TOTAL_TC);

    k_wcopy<<<1024, 256>>>(W1);
    k_bcat<<<64, 256>>>(W2, b1, b2);
    dim3 wg(8, 8);
    k_w21<<<wg, 256>>>(W2, W1);
    k_ln<<<T_TOT, 128>>>(hs, gamma, beta);
    dim3 gtc(4, 512);
    k_gemm_tc<<<gtc, 256, SM_TOTAL_TC>>>(batch);
    k_final<<<128, 512>>>(out);
}

// round 7
// speedup vs baseline: 2.4522x; 1.1646x over previous
#include <cuda_runtime.h>
#include <cuda_fp16.h>
#include <cstdint>
#include <cstddef>

// Problem constants (fixed by dataset)
#define T_TOT 131072
#define CDIM  512
#define NF    1024   // interleaved [y_0,z_0,y_1,z_1,...]  (y=W1 path, z=W2W1 path)
#define BATCH 128

// tcgen05 requires the sm_103a ("arch-accelerated") target pass.
#if defined(__CUDA_ARCH_FEAT_SM103_ALL)
#define HAS_TC 1
#else
#define HAS_TC 0
#endif

// ---------------- scratch: __device__ globals (no allocation allowed) ----------------
// Tiled + pre-swizzled layouts (32 KB blocks = smem images for cp.async.bulk):
// A block (row-tile R of 256 rows, K-chunk c): base=(R*8+c)*32768, two 16 KB
//   sub-halves of 128 rows each -> a 128-row CTA uses one 16 KB half directly.
// B block (icol-tile nt of 256, K-chunk c): base=(nt*8+c)*32768.
__device__ __half g_x[(size_t)T_TOT * CDIM];     // LN output fp16, tiled    134 MB
__device__ __half g_wcat[(size_t)NF * CDIM];     // interleaved weights, tiled (1 MB)
__device__ float  g_bcat[NF];                    // interleaved [b1_d ; (W2 b1 + b2)_d]
__device__ float  g_num[BATCH * CDIM];           // Σ w*y per (graph, d)
__device__ float  g_den[BATCH * CDIM];           // Σ w   per (graph, d)

// ---------------- PTX helpers ----------------
__device__ __forceinline__ uint32_t smem_u32(const void* p) {
    return (uint32_t)__cvta_generic_to_shared(p);
}
#define SWZ128(o) ((o) ^ (((o) >> 3) & 0x70))

// ---------------- K1a: W1 row d -> wcat icol 2d (fp16, tiled); zero accumulators ----
__global__ void k_wcopy(const float* __restrict__ W1) {
    int i = blockIdx.x * 256 + threadIdx.x;      // 262144 elements
    int d = i >> 9, k = i & 511;
    int icol = 2 * d;
    int nt = icol >> 8, rloc = icol & 255;
    int c = k >> 6, klocb = (k & 63) * 2;
    size_t base = ((size_t)(nt * 8 + c)) * 32768;
    uint32_t off = SWZ128((uint32_t)(rloc * 128 + klocb));
    *(__half*)((char*)g_wcat + base + off) = __float2half(W1[i]);
    if (i < BATCH * CDIM) { g_num[i] = 0.f; g_den[i] = 0.f; }
}

// ---------------- K1b: bcat interleaved [b1_d ; (W2@b1+b2)_d], warp-per-output ------
__global__ void k_bcat(const float* __restrict__ W2, const float* __restrict__ b1,
                       const float* __restrict__ b2) {
    int w = (blockIdx.x * 256 + threadIdx.x) >> 5;   // 0..511 (grid 64 x 256)
    int lane = threadIdx.x & 31;
    float acc = 0.f;
    const float* row = W2 + (size_t)w * CDIM;
#pragma unroll 4
    for (int j = lane; j < CDIM; j += 32) acc += row[j] * __ldg(&b1[j]);
#pragma unroll
    for (int o = 16; o > 0; o >>= 1) acc += __shfl_xor_sync(0xFFFFFFFFu, acc, o);
    if (lane == 0) {
        g_bcat[2 * w]     = __ldg(&b1[w]);
        g_bcat[2 * w + 1] = acc + __ldg(&b2[w]);
    }
}

// ---------------- K1c: W21 = W2 @ W1 -> wcat icol 2d+1 (fp16, tiled) ----------------
__global__ void __launch_bounds__(256) k_w21(const float* __restrict__ W2,
                                             const float* __restrict__ W1) {
    __shared__ float sA[32][65];
    __shared__ float sB[32][64];
    int t = threadIdx.x;
    int tx = t & 15, ty = t >> 4;
    int d0 = blockIdx.y * 64, k0 = blockIdx.x * 64;
    float acc[4][4] = {};
    for (int jc = 0; jc < CDIM; jc += 32) {
        for (int i = t; i < 64 * 32; i += 256) {
            int r = i >> 5, j = i & 31;
            sA[j][r] = W2[(size_t)(d0 + r) * CDIM + jc + j];
        }
        for (int i = t; i < 32 * 64; i += 256) {
            int j = i >> 6, c = i & 63;
            sB[j][c] = W1[(size_t)(jc + j) * CDIM + k0 + c];
        }
        __syncthreads();
#pragma unroll
        for (int j = 0; j < 32; j++) {
            float a[4], b[4];
#pragma unroll
            for (int i = 0; i < 4; i++) a[i] = sA[j][ty * 4 + i];
#pragma unroll
            for (int l = 0; l < 4; l++) b[l] = sB[j][tx * 4 + l];
#pragma unroll
            for (int i = 0; i < 4; i++)
#pragma unroll
                for (int l = 0; l < 4; l++) acc[i][l] += a[i] * b[l];
        }
        __syncthreads();
    }
#pragma unroll
    for (int i = 0; i < 4; i++)
#pragma unroll
        for (int l = 0; l < 4; l++) {
            int dr = d0 + ty * 4 + i;
            int k  = k0 + tx * 4 + l;
            int icol = 2 * dr + 1;
            int nt = icol >> 8, rloc = icol & 255;
            int c = k >> 6, klocb = (k & 63) * 2;
            size_t base = ((size_t)(nt * 8 + c)) * 32768;
            uint32_t off = SWZ128((uint32_t)(rloc * 128 + klocb));
            *(__half*)((char*)g_wcat + base + off) = __float2half(acc[i][l]);
        }
}

// ---------------- K2: LayerNorm (eps=1e-5) -> fp16 (tiled + pre-swizzled) -----------
__global__ void k_ln(const float* __restrict__ hs, const float* __restrict__ gamma,
                     const float* __restrict__ beta) {
    __shared__ float s_sum[4], s_sq[4];
    int row = blockIdx.x;
    int t = threadIdx.x;                          // 128 threads, 4 floats each
    const float4 v = __ldg((const float4*)(hs + (size_t)row * CDIM) + t);
    float s = v.x + v.y + v.z + v.w;
    float q = v.x * v.x + v.y * v.y + v.z * v.z + v.w * v.w;
#pragma unroll
    for (int o = 16; o > 0; o >>= 1) {
        s += __shfl_xor_sync(0xFFFFFFFFu, s, o);
        q += __shfl_xor_sync(0xFFFFFFFFu, q, o);
    }
    if ((t & 31) == 0) { s_sum[t >> 5] = s; s_sq[t >> 5] = q; }
    __syncthreads();
    s = s_sum[0] + s_sum[1] + s_sum[2] + s_sum[3];
    q = s_sq[0] + s_sq[1] + s_sq[2] + s_sq[3];
    float mu = s * (1.f / CDIM);
    float var = q * (1.f / CDIM) - mu * mu;
    float rs = rsqrtf(var + 1e-5f);
    float4 g4 = __ldg((const float4*)gamma + t);
    float4 b4 = __ldg((const float4*)beta + t);
    __half2 h0 = __floats2half2_rn((v.x - mu) * rs * g4.x + b4.x,
                                   (v.y - mu) * rs * g4.y + b4.y);
    __half2 h1 = __floats2half2_rn((v.z - mu) * rs * g4.z + b4.z,
                                   (v.w - mu) * rs * g4.w + b4.w);
    uint2 packed;
    packed.x = *(uint32_t*)&h0;
    packed.y = *(uint32_t*)&h1;
    int R = row >> 8, sub = (row >> 7) & 1, rloc = row & 127;
    int c = t >> 4;
    int klocb = (8 * t) & 127;
    size_t base = ((size_t)(R * 8 + c)) * 32768 + (size_t)sub * 16384;
    uint32_t off = SWZ128((uint32_t)(rloc * 128 + klocb));
    *(uint2*)((char*)g_x + base + off) = packed;
}

// ============================================================================
// K3: tcgen05 GEMM + fused softmax-pool epilogue (sm_103a pass only)
// CTA tile M=128 x N=256 icols; grid (4 nt, 1024 Rt128); TMEM 256 cols/CTA,
// 2 CTAs/SM. 2-stage bulk-copy pipeline (warp 0), mbarrier full/empty.
// ============================================================================
#define STG_BYTES 49152           // A 16K | B 32K
#define SM_CTRL   2048
#define SM_TOTAL_TC (SM_CTRL + 2 * STG_BYTES)   // 100352
#define IDESC 0x8400010u          // f16*f16->f32, M=128, N=256

#if HAS_TC
__device__ __forceinline__ uint32_t elect_one_pred() {
    uint32_t pred;
    asm volatile("{\n\t.reg .pred p;\n\telect.sync _|p, 0xFFFFFFFF;\n\tselp.b32 %0, 1, 0, p;\n\t}"
                 : "=r"(pred));
    return pred;
}
static constexpr uint64_t SMEM_DESC_BASE_SW128 =
    (uint64_t(2) << 61) | (uint64_t(1) << 46) | (uint64_t(64) << 32) | (uint64_t(1) << 16);
#define MAKE_SMEM_DESC(b) (SMEM_DESC_BASE_SW128 | ((uint64_t)((b) >> 4) & 0x3FFF))
#define MBARRIER_INIT(a, c) \
    asm volatile("mbarrier.init.shared.b64 [%0], %1;" :: "r"(a), "r"(c) : "memory")
#define MBAR_EXPECT_TX(a, n) \
    asm volatile("mbarrier.arrive.expect_tx.shared.b64 _, [%0], %1;" :: "r"(a), "r"(n) : "memory")
#define MBAR_WAIT(a, ph) do {                                                  \
    asm volatile("{\n\t.reg .pred P1;\n\t"                                     \
        "WL_%=:\n\t"                                                           \
        "mbarrier.try_wait.parity.acquire.cta.shared::cta.b64 P1, [%0], %1, 0x989680;\n\t" \
        "@P1 bra.uni WD_%=;\n\t"                                               \
        "bra.uni WL_%=;\n\t"                                                   \
        "WD_%=:\n\t}" :: "r"(a), "r"(ph) : "memory");                          \
} while (0)
#define BULK_CP(dst, src, n, mbar) \
    asm volatile("cp.async.bulk.shared::cta.global.mbarrier::complete_tx::bytes " \
                 "[%0], [%1], %2, [%3];" \
                 :: "r"(dst), "l"(src), "r"(n), "r"(mbar) : "memory")
__device__ __forceinline__ void mma_f16_ss(uint32_t d_tmem, uint64_t a_desc, uint64_t b_desc,
                                           uint32_t idesc, uint32_t en) {
    uint32_t z = 0;
    asm volatile(
        "{\n\t.reg .pred p;\n\t"
        "setp.ne.u32 p, %5, 0;\n\t"
        "tcgen05.mma.cta_group::1.kind::f16 [%0], %1, %2, %3, {%4, %4, %4, %4}, p;\n\t"
        "}"
        :: "r"(d_tmem), "l"(a_desc), "l"(b_desc), "r"(idesc), "r"(z), "r"(en)
        : "memory");
}
#define LDTM_X32(r, a) \
    asm volatile( \
        "tcgen05.ld.sync.aligned.32x32b.x32.b32 " \
        "{%0, %1, %2, %3, %4, %5, %6, %7, " \
        " %8, %9, %10, %11, %12, %13, %14, %15, " \
        " %16, %17, %18, %19, %20, %21, %22, %23, " \
        " %24, %25, %26, %27, %28, %29, %30, %31}, [%32];" \
        : "=r"((r)[0]),  "=r"((r)[1]),  "=r"((r)[2]),  "=r"((r)[3]), \
          "=r"((r)[4]),  "=r"((r)[5]),  "=r"((r)[6]),  "=r"((r)[7]), \
          "=r"((r)[8]),  "=r"((r)[9]),  "=r"((r)[10]), "=r"((r)[11]), \
          "=r"((r)[12]), "=r"((r)[13]), "=r"((r)[14]), "=r"((r)[15]), \
          "=r"((r)[16]), "=r"((r)[17]), "=r"((r)[18]), "=r"((r)[19]), \
          "=r"((r)[20]), "=r"((r)[21]), "=r"((r)[22]), "=r"((r)[23]), \
          "=r"((r)[24]), "=r"((r)[25]), "=r"((r)[26]), "=r"((r)[27]), \
          "=r"((r)[28]), "=r"((r)[29]), "=r"((r)[30]), "=r"((r)[31]) \
        : "r"(a))
#endif // HAS_TC

__global__ void __launch_bounds__(256, 2) k_gemm_tc(const int* __restrict__ batch) {
#if HAS_TC
    extern __shared__ char sm[];
    const uint32_t smb = smem_u32(sm);
    const int tid = threadIdx.x;
    const int lane = tid & 31, wid = tid >> 5;
    const int nt = blockIdx.x;                 // icol tile (0..3)
    const int rt = blockIdx.y;                 // 128-row tile (0..1023)
    const int n0 = nt * 256;
    const int row0 = rt * 128;
    int* s_bat = (int*)(sm + 1024);            // 128 ints

    // mbar layout: full[s] @ smb+8+s*8 (s<2), empty[s] @ smb+24+s*8
    if (wid == 0) {
        asm volatile("tcgen05.alloc.cta_group::1.sync.aligned.shared::cta.b32 [%0], %1;"
                     :: "r"(smb), "r"(256) : "memory");
        asm volatile("tcgen05.relinquish_alloc_permit.cta_group::1.sync.aligned;");
    }
    if (tid == 0) {
#pragma unroll
        for (int s = 0; s < 2; s++) {
            MBARRIER_INIT(smb + 8 + s * 8, 1);
            MBARRIER_INIT(smb + 24 + s * 8, 1);
        }
    }
    if (tid < 128) s_bat[tid] = __ldg(&batch[row0 + tid]);
    __syncthreads();
    uint32_t tmem;
    asm volatile("ld.shared.b32 %0, [%1];" : "=r"(tmem) : "r"(smb));

    if (wid == 0) {
        // A: 16 KB half-block of row-tile rt: base (rt/2 * 8 + c)*32768 + (rt&1)*16384
        const char* Abase = (const char*)g_x    + (size_t)(rt >> 1) * 8 * 32768
                                                + (size_t)(rt & 1) * 16384;
        const char* Bbase = (const char*)g_wcat + (size_t)nt * 8 * 32768;
        const uint32_t ep = elect_one_pred();

        auto issue_load = [&](int c, int s) {
            const uint32_t stg = smb + SM_CTRL + s * STG_BYTES;
            const uint32_t fm = smb + 8 + s * 8;
            MBAR_EXPECT_TX(fm, 49152u);
            BULK_CP(stg,          Abase + (size_t)c * 32768, 16384u, fm);
            BULK_CP(stg + 16384u, Bbase + (size_t)c * 32768, 32768u, fm);
        };

        if (ep) { issue_load(0, 0); issue_load(1, 1); }

        for (int c = 0; c < 8; c++) {
            const int s = c & 1;
            const int ph = (c >> 1) & 1;
            MBAR_WAIT(smb + 8 + s * 8, ph);        // stage data ready
            if (ep) {
                const uint32_t stg = smb + SM_CTRL + s * STG_BYTES;
                uint64_t dA = MAKE_SMEM_DESC(stg);
                uint64_t dB = MAKE_SMEM_DESC(stg + 16384u);
#pragma unroll
                for (int ks = 0; ks < 4; ks++) {
                    uint32_t en = (c > 0 || ks > 0) ? 1u : 0u;
                    mma_f16_ss(tmem, dA + ks * 2, dB + ks * 2, IDESC, en);
                }
                asm volatile("tcgen05.commit.cta_group::1.mbarrier::arrive::one.shared::cluster.b64 [%0];"
                             :: "r"(smb + 24 + s * 8) : "memory");
            }
            if (c + 2 < 8) {
                MBAR_WAIT(smb + 24 + s * 8, ph);   // MMA(c) done with stage s
                if (ep) issue_load(c + 2, s);
            }
        }
        // final: 4th commit on each stage (parity 1)
        MBAR_WAIT(smb + 24 + 0 * 8, 1);            // c=6
        MBAR_WAIT(smb + 24 + 1 * 8, 1);            // c=7
    }
    __syncthreads();
    asm volatile("tcgen05.fence::after_thread_sync;" ::: "memory");

    // ---- fused epilogue: two warpgroups on disjoint 64-feature halves ----
    const int wg = wid >> 2;                       // warpgroup 0/1
    const int wg_tid = tid & 127;
    float* s_num = (float*)(sm + SM_CTRL) + wg * (128 * 33 * 2);
    float* s_den = s_num + 128 * 33;
    const int rloc = (wid & 3) * 32 + lane;        // row within 128
    const int dscan = wg_tid & 31, gscan = wg_tid >> 5;

#pragma unroll 1
    for (int p = 0; p < 2; p++) {                  // 2 passes x 32 features per wg
        const int f0 = wg * 64 + p * 32;
        uint32_t rr[64];
        LDTM_X32(rr,      tmem + 2 * f0);
        LDTM_X32(rr + 32, tmem + 2 * f0 + 32);
        asm volatile("tcgen05.wait::ld.sync.aligned;" ::: "memory");
#pragma unroll
        for (int i = 0; i < 32; i++) {
            float y = __uint_as_float(rr[2 * i])     + __ldg(&g_bcat[n0 + 2 * (f0 + i)]);
            float z = __uint_as_float(rr[2 * i + 1]) + __ldg(&g_bcat[n0 + 2 * (f0 + i) + 1]);
            float w = __expf(z);
            s_num[rloc * 33 + i] = w * y;
            s_den[rloc * 33 + i] = w;
        }
        __syncthreads();
        {
            int dglob = (n0 >> 1) + f0 + dscan;
            float an = 0.f, ad = 0.f;
            int curb = s_bat[gscan * 32];
#pragma unroll 4
            for (int r = 0; r < 32; r++) {
                int rr2 = gscan * 32 + r;
                int bb = s_bat[rr2];
                if (bb != curb) {
                    atomicAdd(&g_num[curb * CDIM + dglob], an);
                    atomicAdd(&g_den[curb * CDIM + dglob], ad);
                    an = 0.f; ad = 0.f; curb = bb;
                }
                an += s_num[rr2 * 33 + dscan];
                ad += s_den[rr2 * 33 + dscan];
            }
            atomicAdd(&g_num[curb * CDIM + dglob], an);
            atomicAdd(&g_den[curb * CDIM + dglob], ad);
        }
        __syncthreads();
    }
    if (wid == 0)
        asm volatile("tcgen05.dealloc.cta_group::1.sync.aligned.b32 %0, %1;" :: "r"(tmem), "r"(256));
#endif // HAS_TC
}

// ---------------- K4: finalize out = num / den ----------------
__global__ void k_final(float* __restrict__ out) {
    int i = blockIdx.x * 512 + threadIdx.x;
    float den = g_den[i];
    out[i] = (den > 0.f) ? (g_num[i] / den) : 0.f;
}

// ---------------- host launcher ----------------
extern "C" void kernel_launch(void* const* d_in, const int* in_sizes, int n_in,
                              void* d_out, int out_size) {
    const float* hs    = (const float*)d_in[0];
    const int*   batch = (const int*)d_in[1];
    // d_in[2] = max_nodes (unused)
    const float* gamma = (const float*)d_in[3];
    const float* beta  = (const float*)d_in[4];
    const float* W1    = (const float*)d_in[5];
    const float* b1    = (const float*)d_in[6];
    const float* W2    = (const float*)d_in[7];
    const float* b2    = (const float*)d_in[8];
    float* out = (float*)d_out;

    cudaFuncSetAttribute(k_gemm_tc, cudaFuncAttributeMaxDynamicSharedMemorySize, SM_TOTAL_TC);

    k_wcopy<<<1024, 256>>>(W1);
    k_bcat<<<64, 256>>>(W2, b1, b2);
    dim3 wg(8, 8);
    k_w21<<<wg, 256>>>(W2, W1);
    k_ln<<<T_TOT, 128>>>(hs, gamma, beta);
    dim3 gtc(4, 1024);
    k_gemm_tc<<<gtc, 256, SM_TOTAL_TC>>>(batch);
    k_final<<<128, 512>>>(out);
}